// round 15
// baseline (speedup 1.0000x reference)
#include <cuda_runtime.h>
#include <math.h>

// Problem: B=64, V=8, J=17, H=256
// keypoints_gt: (B,V,J,2) float32   -> d_in[0], 17408 elems
// heatmap:      (B,V,1,H,H) float32 -> d_in[1], 33554432 elems
// out: scalar float = mean over B*V*J of -log(hm[b,v, clip(ceil(ky)), clip(ceil(kx))])
//
// Pollerless single-atomic-word design:
//   - 272 uniform single-warp CTAs. Per-thread -log(val) quantized to
//     fixed-point u32 (scale 2^23), warp-summed with ONE redux.sync.add.u32,
//     lane 0 fires ONE atomicAdd(u64) of (1<<48 | warp_sum): arrival count in
//     the high 16 bits, payload in the low 48 bits.
//   - atomicAdd returns the previous value: the warp that sees
//     prev>>48 == NWRK-1 is the LAST arriver and already holds the complete
//     sum (prev_low + own wsum) in a register -> it finalizes and rearms.
//     No poller, no spinning, no fences, no partials array.
//   - determinism: integer adds are associative -> bit-exact every replay.
//   - precision: quant error <= 2^-24 rel/value; total < 2^40 fits 48 bits.

#define NTOT   8704      // 64*8*17
#define JDIM   17
#define HDIM   256
#define NBLK   272       // 272 * 32 = 8704 exactly; one warp per block
#define NTHR   32
#define FXSCALE 8388608.0f   // 2^23

__device__ unsigned long long g_acc;   // zero-init at load; last arriver rearms

__device__ __forceinline__ void st_relaxed_u64(unsigned long long* p, unsigned long long v) {
    asm volatile("st.relaxed.gpu.global.u64 [%0], %1;" :: "l"(p), "l"(v) : "memory");
}
__device__ __forceinline__ unsigned int redux_add_u32(unsigned int v) {
    unsigned int r;
    asm volatile("redux.sync.add.u32 %0, %1, 0xFFFFFFFF;" : "=r"(r) : "r"(v));
    return r;
}

__global__ __launch_bounds__(NTHR) void heatmap_ce_fused_kernel(
    const float* __restrict__ kp,   // (NTOT, 2)
    const float* __restrict__ hm,   // (B*V, H, H)
    float* __restrict__ out)
{
    const int lane = threadIdx.x;                     // block == warp
    const int i = blockIdx.x * NTHR + lane;           // 0..8703, exact

    // kp-independent base, overlaps kp load latency.
    // Max offset 64*8*65536 = 33.5M < 2^31 -> 32-bit address math.
    const int base = (i / JDIM) * (HDIM * HDIM);      // bv * 65536

    const float2 k = reinterpret_cast<const float2*>(kp)[i];

    int xi = (int)ceilf(k.x);
    int yi = (int)ceilf(k.y);
    xi = min(max(xi, 0), HDIM - 1);
    yi = min(max(yi, 0), HDIM - 1);
    const int off = base + (yi << 8) + xi;

    const float val = __ldg(hm + off);
    const float s = -__logf(val);   // in (0, ~6.91]; fast log within 1e-3 tol

    // fixed-point: s * 2^23 < 2^26; warp sum < 2^31 -> u32 safe
    const unsigned int fx = __float2uint_rn(s * FXSCALE);

    // one-instruction warp reduction (no shfl chain)
    const unsigned int wsum = redux_add_u32(fx);

    if (lane == 0) {
        const unsigned long long prev =
            atomicAdd(&g_acc, (1ULL << 48) | (unsigned long long)wsum);

        if ((prev >> 48) == (unsigned long long)(NBLK - 1)) {
            // LAST arriver: complete sum is prev payload + our contribution.
            const unsigned long long sum_fx =
                (prev & 0xFFFFFFFFFFFFULL) + (unsigned long long)wsum;
            const double mean =
                (double)sum_fx * (1.0 / ((double)FXSCALE * (double)NTOT));
            out[0] = (float)mean;

            st_relaxed_u64(&g_acc, 0ULL);   // rearm for next graph replay
        }
    }
}

extern "C" void kernel_launch(void* const* d_in, const int* in_sizes, int n_in,
                              void* d_out, int out_size)
{
    const float* kp = (const float*)d_in[0];
    const float* hm = (const float*)d_in[1];
    float* out = (float*)d_out;

    heatmap_ce_fused_kernel<<<NBLK, NTHR>>>(kp, hm, out);
}